// round 16
// baseline (speedup 1.0000x reference)
#include <cuda_runtime.h>
#include <cuda_fp16.h>
#include <cstdint>
#include <math.h>

// ---------------------------------------------------------------------------
// Problem constants
#define T_TOK 4096
#define H_DIM 1024
#define I_DIM 2048
#define N_EXP 8
#define K_TOP 2
#define MAXROWS 10240   // 8192 pairs + per-expert padding to 128 => 80 tiles

// GEMM tiling
#define BM 128
#define BN 128
#define BK 32
#define ROWB 80                      // padded smem row: 32 fp16 (64B) + 16B pad
#define TILE_BYTES (128 * ROWB)      // 10240
#define STAGE_BYTES (2 * TILE_BYTES) // A, B fp16 tiles
#define SMEM_TOTAL (2 * STAGE_BYTES) // 40960 -> 2 CTAs/SM
#define NROWT (MAXROWS / BM)         // 80 row tiles

// ---------------------------------------------------------------------------
// Scratch (device globals — allocation-free; referenced ONLY from device code)
// Zero-initialized at module load; tail_kernel restores that state each call.
__device__ int   d_count[N_EXP];
__device__ int   d_cursor[N_EXP];
__device__ int   d_tok[MAXROWS];
__device__ float d_roww[MAXROWS];
__device__ float d_topw[T_TOK * K_TOP];
__device__ int   d_tope[T_TOK * K_TOP];

__device__ unsigned short d_xh[(size_t)T_TOK * H_DIM];            // fp16(x)
// W1 = gate/up interleaved at 8-col granularity: [E][4096][1024] fp16
__device__ unsigned short d_W1h[(size_t)N_EXP * 2 * I_DIM * H_DIM];
// Wd transposed: [E][1024][2048] fp16
__device__ unsigned short d_Wdh[(size_t)N_EXP * H_DIM * I_DIM];
__device__ unsigned short d_midh[(size_t)MAXROWS * I_DIM];        // fp16(mid)

// ---------------------------------------------------------------------------
// PTX macros (baseline PTX only: compiles for compute_103 target)
#define CP16(dst, src, sz) \
    asm volatile("cp.async.cg.shared.global [%0], [%1], 16, %2;" \
                 :: "r"(dst), "l"(src), "r"(sz) : "memory")
#define CP_COMMIT() asm volatile("cp.async.commit_group;" ::: "memory")
#define CP_WAIT0()  asm volatile("cp.async.wait_group 0;" ::: "memory")

#define LDSM_X4(r, addr) \
    asm volatile("ldmatrix.sync.aligned.m8n8.x4.shared.b16 {%0,%1,%2,%3}, [%4];" \
                 : "=r"((r)[0]), "=r"((r)[1]), "=r"((r)[2]), "=r"((r)[3]) : "r"(addr))

#define MMA_F16(c, a, b) \
    asm volatile("mma.sync.aligned.m16n8k16.row.col.f32.f16.f16.f32 " \
                 "{%0,%1,%2,%3}, {%4,%5,%6,%7}, {%8,%9}, {%0,%1,%2,%3};" \
                 : "+f"((c)[0]), "+f"((c)[1]), "+f"((c)[2]), "+f"((c)[3]) \
                 : "r"((a)[0]), "r"((a)[1]), "r"((a)[2]), "r"((a)[3]), \
                   "r"((b)[0]), "r"((b)[1]))

// fp16 helpers
__device__ __forceinline__ unsigned short h16(float v) {
    __half h = __float2half_rn(v);
    return *reinterpret_cast<unsigned short*>(&h);
}
__device__ __forceinline__ float silu_mul(float g, float u) {
    return g / (1.f + expf(-g)) * u;
}

// ---------------------------------------------------------------------------
// Fused pre-kernel: blocks [0,4096) zero the output; blocks [4096,4608) run
// the router (one warp per token) AND write the fp16 conversion of x inline
// with coalesced ushort4 stores (lane owns 4 consecutive columns).
__global__ void pre_kernel(const float* __restrict__ x,
                           const float* __restrict__ gw,
                           float* __restrict__ out,
                           float* __restrict__ out_logits) {
    int b = blockIdx.x;
    if (b < 4096) {
        size_t i = (size_t)b * 256 + threadIdx.x;
        ((float4*)out)[i] = make_float4(0.f, 0.f, 0.f, 0.f);
    } else {
        int warp = threadIdx.x >> 5, lane = threadIdx.x & 31;
        int t = (b - 4096) * 8 + warp;
        if (t >= T_TOK) return;
        const float* xr = x + (size_t)t * H_DIM;
        unsigned short* xh = d_xh + (size_t)t * H_DIM;
        float acc[N_EXP];
#pragma unroll
        for (int e = 0; e < N_EXP; e++) acc[e] = 0.f;
        for (int i = lane * 4; i < H_DIM; i += 128) {
            float4 v = *(const float4*)(xr + i);
            ushort4 h;
            h.x = h16(v.x); h.y = h16(v.y); h.z = h16(v.z); h.w = h16(v.w);
            *(ushort4*)(xh + i) = h;               // fused, coalesced convert
            const float* g0 = gw + (size_t)i * N_EXP;
#pragma unroll
            for (int c = 0; c < 4; c++) {
                float xv = (c == 0) ? v.x : (c == 1) ? v.y : (c == 2) ? v.z : v.w;
                float4 a  = __ldg((const float4*)(g0 + c * N_EXP));
                float4 bb = __ldg((const float4*)(g0 + c * N_EXP) + 1);
                acc[0] += xv * a.x;  acc[1] += xv * a.y;
                acc[2] += xv * a.z;  acc[3] += xv * a.w;
                acc[4] += xv * bb.x; acc[5] += xv * bb.y;
                acc[6] += xv * bb.z; acc[7] += xv * bb.w;
            }
        }
#pragma unroll
        for (int off = 16; off > 0; off >>= 1)
#pragma unroll
            for (int e = 0; e < N_EXP; e++)
                acc[e] += __shfl_xor_sync(0xffffffffu, acc[e], off);
        if (lane == 0) {
#pragma unroll
            for (int e = 0; e < N_EXP; e++) out_logits[(size_t)t * N_EXP + e] = acc[e];
            float m = acc[0];
#pragma unroll
            for (int e = 1; e < N_EXP; e++) m = fmaxf(m, acc[e]);
            float p[N_EXP], s = 0.f;
#pragma unroll
            for (int e = 0; e < N_EXP; e++) { p[e] = expf(acc[e] - m); s += p[e]; }
            float inv = 1.f / s;
            int i0 = 0; float b0 = p[0];
#pragma unroll
            for (int e = 1; e < N_EXP; e++) if (p[e] > b0) { b0 = p[e]; i0 = e; }
            int i1 = -1; float b1 = -1.f;
#pragma unroll
            for (int e = 0; e < N_EXP; e++) if (e != i0 && p[e] > b1) { b1 = p[e]; i1 = e; }
            d_tope[t * 2 + 0] = i0; d_topw[t * 2 + 0] = b0 * inv;
            d_tope[t * 2 + 1] = i1; d_topw[t * 2 + 1] = b1 * inv;
            atomicAdd(&d_count[i0], 1);
            atomicAdd(&d_count[i1], 1);
        }
    }
}

// transpose + fp16 convert with vectorized writes.
// mode 0: Wg -> W1 (interleaved even groups); 1: Wu -> W1 (odd); 2: Wd.
__global__ void wtrans_kernel(const float* __restrict__ W, int mode) {
    __shared__ float tile[64][33];
    const int Kd = (mode == 2) ? I_DIM : H_DIM;
    const int Nd = (mode == 2) ? H_DIM : I_DIM;
    const int Nb = (mode == 2) ? H_DIM : 2 * I_DIM;
    unsigned short* Th = (mode == 2) ? d_Wdh : d_W1h;

    int e = blockIdx.z;
    const float* We = W + (size_t)e * Kd * Nd;
    int nbase = blockIdx.x * 32, kbase = blockIdx.y * 64;
    int tid = threadIdx.x, tx = tid & 31, ty = tid >> 5;
#pragma unroll
    for (int r = 0; r < 64; r += 8)
        tile[r + ty][tx] = We[(size_t)(kbase + r + ty) * Nd + nbase + tx];
    __syncthreads();

    size_t ebase = (size_t)e * Nb * Kd;
#pragma unroll
    for (int task = tid; task < 512; task += 256) {
        int n = task >> 4, q = task & 15;
        int j = nbase + n;
        int np = (mode == 2) ? j
                 : (((j >> 3) << 4) | (mode == 1 ? 8 : 0) | (j & 7));
        ushort4 h;
        h.x = h16(tile[q * 4 + 0][n]);
        h.y = h16(tile[q * 4 + 1][n]);
        h.z = h16(tile[q * 4 + 2][n]);
        h.w = h16(tile[q * 4 + 3][n]);
        size_t o = ebase + (size_t)np * Kd + kbase + q * 4;
        *(ushort4*)(Th + o) = h;
    }
}

// Scatter (blocks 0..15) + padding-sentinel fill (block 16).
__global__ void scatter_kernel() {
    int segs[N_EXP];
    {
        int off = 0;
#pragma unroll
        for (int i = 0; i < N_EXP; i++) { segs[i] = off; off += (d_count[i] + 127) & ~127; }
    }
    int b = blockIdx.x;
    if (b < 16) {
        int t = b * 256 + threadIdx.x;
#pragma unroll
        for (int k = 0; k < K_TOP; k++) {
            int e = d_tope[t * 2 + k];
            int pos = atomicAdd(&d_cursor[e], 1);
            int row = segs[e] + pos;
            d_tok[row] = t;
            d_roww[row] = d_topw[t * 2 + k];
        }
    } else {
#pragma unroll
        for (int e = 0; e < N_EXP; e++) {
            int cnt = d_count[e];
            int pad = (cnt + 127) & ~127;
            for (int r = cnt + threadIdx.x; r < pad; r += 256)
                d_tok[segs[e] + r] = -1;
        }
    }
}

// Reset count/cursor for the next graph replay (runs after GEMM2).
__global__ void tail_kernel() {
    int tid = threadIdx.x;
    if (tid < N_EXP) { d_count[tid] = 0; d_cursor[tid] = 0; }
}

// ---------------------------------------------------------------------------
// Grouped GEMM on mma.sync.m16n8k16 fp16 (single pass), fp32 acc.
// MODE 0: A = gather(x) [K=1024], B = W1 (g/u interleaved), epilogue fuses
//         silu(g)*u -> fp16 -> d_midh  (acc j even = gate, odd = up)
// MODE 1: A = mid [K=2048], B = Wd, epilogue fuses weighted combine:
//         out[token] += w_row * acc  (atomicAdd; 2 adds/element -> deterministic)
// 128x128x32 CTA tile, 8 warps of 64x32, 2-stage cp.async, 2 CTAs/SM,
// single __syncthreads per K-step (prefetch issued after the barrier).
// (R12 mainloop — frozen; BK=64 and 64x64-warp variants both regressed.)
template <int MODE>
__global__ __launch_bounds__(256, 2)
void mma_gemm_kernel(float* __restrict__ out)
{
    constexpr int Kdim = (MODE == 0) ? H_DIM : I_DIM;
    constexpr int Nb   = (MODE == 0) ? 2 * I_DIM : H_DIM;

    extern __shared__ char sm[];
    int row0 = blockIdx.x * BM;

    // segment lookup from counts
    int e = 0;
    {
        int off = 0;
#pragma unroll
        for (int i = 0; i < N_EXP; i++) {
            if (row0 >= off) e = i;
            off += (d_count[i] + 127) & ~127;
        }
        if (row0 >= off) return;
    }

    const unsigned short* __restrict__ A_g = (MODE == 0) ? d_xh : d_midh;
    const unsigned short* __restrict__ B_g = (MODE == 0) ? d_W1h : d_Wdh;

    uint32_t sbase = (uint32_t)__cvta_generic_to_shared(sm);
    int tid = threadIdx.x, lane = tid & 31, wid = tid >> 5;
    int n0 = blockIdx.y * BN;

    // ---- per-thread load setup: 2 rows per tile (r and r+64), 16B chunk kc
    int r1 = tid >> 2, kc = tid & 3;
    const unsigned short *pA[2], *pB[2];
    uint32_t szA[2], dstoff[2];
#pragma unroll
    for (int h2 = 0; h2 < 2; h2++) {
        int r = r1 + h2 * 64;
        dstoff[h2] = (uint32_t)(r * ROWB + kc * 16);
        if (MODE == 0) {
            int tok = d_tok[row0 + r];
            pA[h2] = (tok >= 0) ? A_g + (size_t)tok * Kdim + kc * 8 : A_g;
            szA[h2] = (tok >= 0) ? 16 : 0;
        } else {
            pA[h2] = A_g + (size_t)(row0 + r) * Kdim + kc * 8;
            szA[h2] = 16;
        }
        pB[h2] = B_g + ((size_t)e * Nb + n0 + r) * Kdim + kc * 8;
    }

#define LOAD_STAGE(s, kof) do { \
    uint32_t sb_ = sbase + (s) * STAGE_BYTES; \
    _Pragma("unroll") \
    for (int h2 = 0; h2 < 2; h2++) { \
        CP16(sb_ + dstoff[h2],              pA[h2] + (kof), szA[h2]); \
        CP16(sb_ + TILE_BYTES + dstoff[h2], pB[h2] + (kof), 16u); \
    } \
} while (0)

    // ---- compute setup
    int wm = (wid & 1) * 64, wn = (wid >> 1) * 32;
    uint32_t a_off = (uint32_t)((wm + (lane & 15)) * ROWB + (lane >> 4) * 16);
    uint32_t b_off = (uint32_t)((wn + (lane & 7) + ((lane >> 4) << 3)) * ROWB +
                                ((lane >> 3) & 1) * 16);

    float acc[4][4][4];
#pragma unroll
    for (int i = 0; i < 4; i++)
#pragma unroll
        for (int j = 0; j < 4; j++)
#pragma unroll
            for (int q = 0; q < 4; q++) acc[i][j][q] = 0.f;

    const int nk = Kdim / BK;
    LOAD_STAGE(0, 0);
    CP_COMMIT();

    for (int ks = 0; ks < nk; ks++) {
        int s = ks & 1;
        CP_WAIT0();          // only stage ks's group can be pending
        __syncthreads();     // everyone done computing stage s^1 (prev iter)

        if (ks + 1 < nk) {
            LOAD_STAGE(s ^ 1, (ks + 1) * BK);  // safe: issued after barrier
            CP_COMMIT();
        }

        uint32_t sb = sbase + s * STAGE_BYTES;
#pragma unroll
        for (int h = 0; h < 2; h++) {  // two k16 steps per BK=32
            uint32_t bh[4][2];
#pragma unroll
            for (int jp = 0; jp < 2; jp++) {
                uint32_t tmp[4];
                LDSM_X4(tmp, sb + TILE_BYTES + b_off + jp * (16 * ROWB) + h * 32);
                bh[jp * 2][0] = tmp[0]; bh[jp * 2][1] = tmp[1];
                bh[jp * 2 + 1][0] = tmp[2]; bh[jp * 2 + 1][1] = tmp[3];
            }
#pragma unroll
            for (int i = 0; i < 4; i++) {
                uint32_t ah[4];
                LDSM_X4(ah, sb + a_off + i * (16 * ROWB) + h * 32);
#pragma unroll
                for (int j = 0; j < 4; j++)
                    MMA_F16(acc[i][j], ah, bh[j]);
            }
        }
    }

    // ---- epilogue
    int rin = lane >> 2, cin = (lane & 3) * 2;
    if (MODE == 0) {
        // acc[i][jp*2] = gate, acc[i][jp*2+1] = up for the SAME logical cols
        int midcol0 = (n0 + wn) >> 1;  // logical mid col base for this warp
#pragma unroll
        for (int i = 0; i < 4; i++)
#pragma unroll
            for (int jp = 0; jp < 2; jp++) {
                const float* g = acc[i][jp * 2];
                const float* u = acc[i][jp * 2 + 1];
                int colb = midcol0 + jp * 8 + cin;
#pragma unroll
                for (int hf = 0; hf < 2; hf++) {
                    float m0 = silu_mul(g[hf * 2 + 0], u[hf * 2 + 0]);
                    float m1 = silu_mul(g[hf * 2 + 1], u[hf * 2 + 1]);
                    ushort2 h2v;
                    h2v.x = h16(m0); h2v.y = h16(m1);
                    size_t off = (size_t)(row0 + wm + i * 16 + rin + hf * 8) * I_DIM + colb;
                    *(ushort2*)(d_midh + off) = h2v;
                }
            }
    } else {
        // fused combine: out[token] += w_row * acc  (2 adds/element total)
        int   tokA[4], tokB[4];
        float wA[4], wB[4];
#pragma unroll
        for (int i = 0; i < 4; i++) {
            int rr = row0 + wm + i * 16 + rin;
            tokA[i] = d_tok[rr];     wA[i] = d_roww[rr];
            tokB[i] = d_tok[rr + 8]; wB[i] = d_roww[rr + 8];
        }
#pragma unroll
        for (int i = 0; i < 4; i++)
#pragma unroll
            for (int j = 0; j < 4; j++) {
                int col = n0 + wn + j * 8 + cin;
                if (tokA[i] >= 0) {
                    float* p = out + (size_t)tokA[i] * H_DIM + col;
                    atomicAdd(p,     wA[i] * acc[i][j][0]);
                    atomicAdd(p + 1, wA[i] * acc[i][j][1]);
                }
                if (tokB[i] >= 0) {
                    float* p = out + (size_t)tokB[i] * H_DIM + col;
                    atomicAdd(p,     wB[i] * acc[i][j][2]);
                    atomicAdd(p + 1, wB[i] * acc[i][j][3]);
                }
            }
    }
#undef LOAD_STAGE
}

// ---------------------------------------------------------------------------
extern "C" void kernel_launch(void* const* d_in, const int* in_sizes, int n_in,
                              void* d_out, int out_size) {
    const float* x  = (const float*)d_in[0];  // [4096, 1024]
    const float* gw = (const float*)d_in[1];  // [1024, 8]
    const float* Wg = (const float*)d_in[2];  // [8, 1024, 2048]
    const float* Wu = (const float*)d_in[3];  // [8, 1024, 2048]
    const float* Wd = (const float*)d_in[4];  // [8, 2048, 1024]
    float* out = (float*)d_out;               // final (4194304) then logits (32768)
    float* out_logits = out + (size_t)T_TOK * H_DIM;

    static cudaStream_t s_side = nullptr;
    static cudaEvent_t ev_fork = nullptr, ev_w1 = nullptr, ev_wd = nullptr;
    if (!s_side) {
        cudaStreamCreateWithFlags(&s_side, cudaStreamNonBlocking);
        cudaEventCreateWithFlags(&ev_fork, cudaEventDisableTiming);
        cudaEventCreateWithFlags(&ev_w1, cudaEventDisableTiming);
        cudaEventCreateWithFlags(&ev_wd, cudaEventDisableTiming);
        cudaFuncSetAttribute(mma_gemm_kernel<0>, cudaFuncAttributeMaxDynamicSharedMemorySize, SMEM_TOTAL);
        cudaFuncSetAttribute(mma_gemm_kernel<1>, cudaFuncAttributeMaxDynamicSharedMemorySize, SMEM_TOTAL);
    }

    // Fork: weight transposes on a side stream. GEMM1 needs only W1 (Wg+Wu);
    // Wd transposes during GEMM1 and gates only GEMM2 (split join events).
    cudaEventRecord(ev_fork, 0);
    cudaStreamWaitEvent(s_side, ev_fork, 0);
    wtrans_kernel<<<dim3(I_DIM / 32, H_DIM / 64, N_EXP), 256, 0, s_side>>>(Wg, 0);
    wtrans_kernel<<<dim3(I_DIM / 32, H_DIM / 64, N_EXP), 256, 0, s_side>>>(Wu, 1);
    cudaEventRecord(ev_w1, s_side);
    wtrans_kernel<<<dim3(H_DIM / 32, I_DIM / 64, N_EXP), 256, 0, s_side>>>(Wd, 2);
    cudaEventRecord(ev_wd, s_side);

    // Main stream: fused zero + router(+coalesced x convert), then scatter
    pre_kernel<<<4608, 256>>>(x, gw, out, out_logits);
    scatter_kernel<<<17, 256>>>();

    // GEMM1 (fused act): needs W1 only
    cudaStreamWaitEvent(0, ev_w1, 0);
    mma_gemm_kernel<0><<<dim3(NROWT, (2 * I_DIM) / BN), 256, SMEM_TOTAL>>>(nullptr);
    // GEMM2 (fused combine): needs Wd
    cudaStreamWaitEvent(0, ev_wd, 0);
    mma_gemm_kernel<1><<<dim3(NROWT, H_DIM / BN), 256, SMEM_TOTAL>>>(out);

    // Reset dispatch state for the next (graph-replayed) call
    tail_kernel<<<1, 32>>>();
}

// round 17
// speedup vs baseline: 1.0455x; 1.0455x over previous
#include <cuda_runtime.h>
#include <cuda_fp16.h>
#include <cstdint>
#include <math.h>

// ---------------------------------------------------------------------------
// Problem constants
#define T_TOK 4096
#define H_DIM 1024
#define I_DIM 2048
#define N_EXP 8
#define K_TOP 2
#define MAXROWS 10240   // 8192 pairs + per-expert padding to 128 => 80 tiles

// GEMM tiling
#define BM 128
#define BN 128
#define BK 32
#define ROWB 80                      // padded smem row: 32 fp16 (64B) + 16B pad
#define TILE_BYTES (128 * ROWB)      // 10240
#define STAGE_BYTES (2 * TILE_BYTES) // A, B fp16 tiles
#define SMEM_TOTAL (2 * STAGE_BYTES) // 40960 -> 2 CTAs/SM
#define NROWT (MAXROWS / BM)         // 80 row tiles

// ---------------------------------------------------------------------------
// Scratch (device globals — allocation-free; referenced ONLY from device code)
// Zero-initialized at module load; tail_kernel restores that state each call.
__device__ int   d_count[N_EXP];
__device__ int   d_cursor[N_EXP];
__device__ int   d_tok[MAXROWS];
__device__ float d_roww[MAXROWS];
__device__ float d_topw[T_TOK * K_TOP];
__device__ int   d_tope[T_TOK * K_TOP];

__device__ unsigned short d_xh[(size_t)T_TOK * H_DIM];            // fp16(x)
// W1 = gate/up interleaved at 8-col granularity: [E][4096][1024] fp16
__device__ unsigned short d_W1h[(size_t)N_EXP * 2 * I_DIM * H_DIM];
// Wd transposed: [E][1024][2048] fp16
__device__ unsigned short d_Wdh[(size_t)N_EXP * H_DIM * I_DIM];
__device__ unsigned short d_midh[(size_t)MAXROWS * I_DIM];        // fp16(mid)

// ---------------------------------------------------------------------------
// PTX macros (baseline PTX only: compiles for compute_103 target)
#define CP16(dst, src, sz) \
    asm volatile("cp.async.cg.shared.global [%0], [%1], 16, %2;" \
                 :: "r"(dst), "l"(src), "r"(sz) : "memory")
#define CP_COMMIT() asm volatile("cp.async.commit_group;" ::: "memory")
#define CP_WAIT0()  asm volatile("cp.async.wait_group 0;" ::: "memory")

#define LDSM_X4(r, addr) \
    asm volatile("ldmatrix.sync.aligned.m8n8.x4.shared.b16 {%0,%1,%2,%3}, [%4];" \
                 : "=r"((r)[0]), "=r"((r)[1]), "=r"((r)[2]), "=r"((r)[3]) : "r"(addr))

#define MMA_F16(c, a, b) \
    asm volatile("mma.sync.aligned.m16n8k16.row.col.f32.f16.f16.f32 " \
                 "{%0,%1,%2,%3}, {%4,%5,%6,%7}, {%8,%9}, {%0,%1,%2,%3};" \
                 : "+f"((c)[0]), "+f"((c)[1]), "+f"((c)[2]), "+f"((c)[3]) \
                 : "r"((a)[0]), "r"((a)[1]), "r"((a)[2]), "r"((a)[3]), \
                   "r"((b)[0]), "r"((b)[1]))

// fp16 helpers
__device__ __forceinline__ unsigned short h16(float v) {
    __half h = __float2half_rn(v);
    return *reinterpret_cast<unsigned short*>(&h);
}
__device__ __forceinline__ float silu_mul(float g, float u) {
    return g / (1.f + expf(-g)) * u;
}

// ---------------------------------------------------------------------------
// Fused pre-kernel (R12 layout — do not "vectorize" the router loop; the
// strided per-lane pattern is what keeps gw/x accesses coalesced):
// blocks [0,4096) zero the output, [4096,8192) convert x, [8192,8704) router.
__global__ void pre_kernel(const float* __restrict__ x,
                           const float* __restrict__ gw,
                           float* __restrict__ out,
                           float* __restrict__ out_logits) {
    int b = blockIdx.x;
    if (b < 4096) {
        size_t i = (size_t)b * 256 + threadIdx.x;
        ((float4*)out)[i] = make_float4(0.f, 0.f, 0.f, 0.f);
    } else if (b < 8192) {
        size_t i = (size_t)(b - 4096) * 256 + threadIdx.x;
        float4 v = ((const float4*)x)[i];
        ushort4 h;
        h.x = h16(v.x); h.y = h16(v.y); h.z = h16(v.z); h.w = h16(v.w);
        ((ushort4*)d_xh)[i] = h;
    } else {
        int warp = threadIdx.x >> 5, lane = threadIdx.x & 31;
        int t = (b - 8192) * 8 + warp;
        if (t >= T_TOK) return;
        const float* xr = x + (size_t)t * H_DIM;
        float acc[N_EXP];
#pragma unroll
        for (int e = 0; e < N_EXP; e++) acc[e] = 0.f;
        for (int i = lane; i < H_DIM; i += 32) {
            float xv = xr[i];
            float4 a = __ldg((const float4*)(gw + (size_t)i * N_EXP));
            float4 bb = __ldg((const float4*)(gw + (size_t)i * N_EXP) + 1);
            acc[0] += xv * a.x; acc[1] += xv * a.y; acc[2] += xv * a.z; acc[3] += xv * a.w;
            acc[4] += xv * bb.x; acc[5] += xv * bb.y; acc[6] += xv * bb.z; acc[7] += xv * bb.w;
        }
#pragma unroll
        for (int off = 16; off > 0; off >>= 1)
#pragma unroll
            for (int e = 0; e < N_EXP; e++)
                acc[e] += __shfl_xor_sync(0xffffffffu, acc[e], off);
        if (lane == 0) {
#pragma unroll
            for (int e = 0; e < N_EXP; e++) out_logits[(size_t)t * N_EXP + e] = acc[e];
            float m = acc[0];
#pragma unroll
            for (int e = 1; e < N_EXP; e++) m = fmaxf(m, acc[e]);
            float p[N_EXP], s = 0.f;
#pragma unroll
            for (int e = 0; e < N_EXP; e++) { p[e] = expf(acc[e] - m); s += p[e]; }
            float inv = 1.f / s;
            int i0 = 0; float b0 = p[0];
#pragma unroll
            for (int e = 1; e < N_EXP; e++) if (p[e] > b0) { b0 = p[e]; i0 = e; }
            int i1 = -1; float b1 = -1.f;
#pragma unroll
            for (int e = 0; e < N_EXP; e++) if (e != i0 && p[e] > b1) { b1 = p[e]; i1 = e; }
            d_tope[t * 2 + 0] = i0; d_topw[t * 2 + 0] = b0 * inv;
            d_tope[t * 2 + 1] = i1; d_topw[t * 2 + 1] = b1 * inv;
            atomicAdd(&d_count[i0], 1);
            atomicAdd(&d_count[i1], 1);
        }
    }
}

// transpose + fp16 convert with vectorized writes.
// mode 0: Wg -> W1 (interleaved even groups); 1: Wu -> W1 (odd); 2: Wd.
__global__ void wtrans_kernel(const float* __restrict__ W, int mode) {
    __shared__ float tile[64][33];
    const int Kd = (mode == 2) ? I_DIM : H_DIM;
    const int Nd = (mode == 2) ? H_DIM : I_DIM;
    const int Nb = (mode == 2) ? H_DIM : 2 * I_DIM;
    unsigned short* Th = (mode == 2) ? d_Wdh : d_W1h;

    int e = blockIdx.z;
    const float* We = W + (size_t)e * Kd * Nd;
    int nbase = blockIdx.x * 32, kbase = blockIdx.y * 64;
    int tid = threadIdx.x, tx = tid & 31, ty = tid >> 5;
#pragma unroll
    for (int r = 0; r < 64; r += 8)
        tile[r + ty][tx] = We[(size_t)(kbase + r + ty) * Nd + nbase + tx];
    __syncthreads();

    size_t ebase = (size_t)e * Nb * Kd;
#pragma unroll
    for (int task = tid; task < 512; task += 256) {
        int n = task >> 4, q = task & 15;
        int j = nbase + n;
        int np = (mode == 2) ? j
                 : (((j >> 3) << 4) | (mode == 1 ? 8 : 0) | (j & 7));
        ushort4 h;
        h.x = h16(tile[q * 4 + 0][n]);
        h.y = h16(tile[q * 4 + 1][n]);
        h.z = h16(tile[q * 4 + 2][n]);
        h.w = h16(tile[q * 4 + 3][n]);
        size_t o = ebase + (size_t)np * Kd + kbase + q * 4;
        *(ushort4*)(Th + o) = h;
    }
}

// Scatter (blocks 0..15) + padding-sentinel fill (block 16).
__global__ void scatter_kernel() {
    int segs[N_EXP];
    {
        int off = 0;
#pragma unroll
        for (int i = 0; i < N_EXP; i++) { segs[i] = off; off += (d_count[i] + 127) & ~127; }
    }
    int b = blockIdx.x;
    if (b < 16) {
        int t = b * 256 + threadIdx.x;
#pragma unroll
        for (int k = 0; k < K_TOP; k++) {
            int e = d_tope[t * 2 + k];
            int pos = atomicAdd(&d_cursor[e], 1);
            int row = segs[e] + pos;
            d_tok[row] = t;
            d_roww[row] = d_topw[t * 2 + k];
        }
    } else {
#pragma unroll
        for (int e = 0; e < N_EXP; e++) {
            int cnt = d_count[e];
            int pad = (cnt + 127) & ~127;
            for (int r = cnt + threadIdx.x; r < pad; r += 256)
                d_tok[segs[e] + r] = -1;
        }
    }
}

// Reset count/cursor for the next graph replay (runs after GEMM2).
__global__ void tail_kernel() {
    int tid = threadIdx.x;
    if (tid < N_EXP) { d_count[tid] = 0; d_cursor[tid] = 0; }
}

// ---------------------------------------------------------------------------
// Grouped GEMM on mma.sync.m16n8k16 fp16 (single pass), fp32 acc.
// MODE 0: A = gather(x) [K=1024], B = W1 (g/u interleaved), epilogue fuses
//         silu(g)*u -> fp16 -> d_midh  (acc j even = gate, odd = up)
// MODE 1: A = mid [K=2048], B = Wd, epilogue fuses weighted combine:
//         out[token] += w_row * acc  (atomicAdd; 2 adds/element -> deterministic)
// 128x128x32 CTA tile, 8 warps of 64x32, 2-stage cp.async, 2 CTAs/SM,
// single __syncthreads per K-step (prefetch issued after the barrier).
// (R12 mainloop — frozen.)
template <int MODE>
__global__ __launch_bounds__(256, 2)
void mma_gemm_kernel(float* __restrict__ out)
{
    constexpr int Kdim = (MODE == 0) ? H_DIM : I_DIM;
    constexpr int Nb   = (MODE == 0) ? 2 * I_DIM : H_DIM;

    extern __shared__ char sm[];
    int row0 = blockIdx.x * BM;

    // segment lookup from counts
    int e = 0;
    {
        int off = 0;
#pragma unroll
        for (int i = 0; i < N_EXP; i++) {
            if (row0 >= off) e = i;
            off += (d_count[i] + 127) & ~127;
        }
        if (row0 >= off) return;
    }

    const unsigned short* __restrict__ A_g = (MODE == 0) ? d_xh : d_midh;
    const unsigned short* __restrict__ B_g = (MODE == 0) ? d_W1h : d_Wdh;

    uint32_t sbase = (uint32_t)__cvta_generic_to_shared(sm);
    int tid = threadIdx.x, lane = tid & 31, wid = tid >> 5;
    int n0 = blockIdx.y * BN;

    // ---- per-thread load setup: 2 rows per tile (r and r+64), 16B chunk kc
    int r1 = tid >> 2, kc = tid & 3;
    const unsigned short *pA[2], *pB[2];
    uint32_t szA[2], dstoff[2];
#pragma unroll
    for (int h2 = 0; h2 < 2; h2++) {
        int r = r1 + h2 * 64;
        dstoff[h2] = (uint32_t)(r * ROWB + kc * 16);
        if (MODE == 0) {
            int tok = d_tok[row0 + r];
            pA[h2] = (tok >= 0) ? A_g + (size_t)tok * Kdim + kc * 8 : A_g;
            szA[h2] = (tok >= 0) ? 16 : 0;
        } else {
            pA[h2] = A_g + (size_t)(row0 + r) * Kdim + kc * 8;
            szA[h2] = 16;
        }
        pB[h2] = B_g + ((size_t)e * Nb + n0 + r) * Kdim + kc * 8;
    }

#define LOAD_STAGE(s, kof) do { \
    uint32_t sb_ = sbase + (s) * STAGE_BYTES; \
    _Pragma("unroll") \
    for (int h2 = 0; h2 < 2; h2++) { \
        CP16(sb_ + dstoff[h2],              pA[h2] + (kof), szA[h2]); \
        CP16(sb_ + TILE_BYTES + dstoff[h2], pB[h2] + (kof), 16u); \
    } \
} while (0)

    // ---- compute setup
    int wm = (wid & 1) * 64, wn = (wid >> 1) * 32;
    uint32_t a_off = (uint32_t)((wm + (lane & 15)) * ROWB + (lane >> 4) * 16);
    uint32_t b_off = (uint32_t)((wn + (lane & 7) + ((lane >> 4) << 3)) * ROWB +
                                ((lane >> 3) & 1) * 16);

    float acc[4][4][4];
#pragma unroll
    for (int i = 0; i < 4; i++)
#pragma unroll
        for (int j = 0; j < 4; j++)
#pragma unroll
            for (int q = 0; q < 4; q++) acc[i][j][q] = 0.f;

    const int nk = Kdim / BK;
    LOAD_STAGE(0, 0);
    CP_COMMIT();

    for (int ks = 0; ks < nk; ks++) {
        int s = ks & 1;
        CP_WAIT0();          // only stage ks's group can be pending
        __syncthreads();     // everyone done computing stage s^1 (prev iter)

        if (ks + 1 < nk) {
            LOAD_STAGE(s ^ 1, (ks + 1) * BK);  // safe: issued after barrier
            CP_COMMIT();
        }

        uint32_t sb = sbase + s * STAGE_BYTES;
#pragma unroll
        for (int h = 0; h < 2; h++) {  // two k16 steps per BK=32
            uint32_t bh[4][2];
#pragma unroll
            for (int jp = 0; jp < 2; jp++) {
                uint32_t tmp[4];
                LDSM_X4(tmp, sb + TILE_BYTES + b_off + jp * (16 * ROWB) + h * 32);
                bh[jp * 2][0] = tmp[0]; bh[jp * 2][1] = tmp[1];
                bh[jp * 2 + 1][0] = tmp[2]; bh[jp * 2 + 1][1] = tmp[3];
            }
#pragma unroll
            for (int i = 0; i < 4; i++) {
                uint32_t ah[4];
                LDSM_X4(ah, sb + a_off + i * (16 * ROWB) + h * 32);
#pragma unroll
                for (int j = 0; j < 4; j++)
                    MMA_F16(acc[i][j], ah, bh[j]);
            }
        }
    }

    // ---- epilogue
    int rin = lane >> 2, cin = (lane & 3) * 2;
    if (MODE == 0) {
        // acc[i][jp*2] = gate, acc[i][jp*2+1] = up for the SAME logical cols
        int midcol0 = (n0 + wn) >> 1;  // logical mid col base for this warp
#pragma unroll
        for (int i = 0; i < 4; i++)
#pragma unroll
            for (int jp = 0; jp < 2; jp++) {
                const float* g = acc[i][jp * 2];
                const float* u = acc[i][jp * 2 + 1];
                int colb = midcol0 + jp * 8 + cin;
#pragma unroll
                for (int hf = 0; hf < 2; hf++) {
                    float m0 = silu_mul(g[hf * 2 + 0], u[hf * 2 + 0]);
                    float m1 = silu_mul(g[hf * 2 + 1], u[hf * 2 + 1]);
                    ushort2 h2v;
                    h2v.x = h16(m0); h2v.y = h16(m1);
                    size_t off = (size_t)(row0 + wm + i * 16 + rin + hf * 8) * I_DIM + colb;
                    *(ushort2*)(d_midh + off) = h2v;
                }
            }
    } else {
        // fused combine: out[token] += w_row * acc  (2 adds/element total)
        int   tokA[4], tokB[4];
        float wA[4], wB[4];
#pragma unroll
        for (int i = 0; i < 4; i++) {
            int rr = row0 + wm + i * 16 + rin;
            tokA[i] = d_tok[rr];     wA[i] = d_roww[rr];
            tokB[i] = d_tok[rr + 8]; wB[i] = d_roww[rr + 8];
        }
#pragma unroll
        for (int i = 0; i < 4; i++)
#pragma unroll
            for (int j = 0; j < 4; j++) {
                int col = n0 + wn + j * 8 + cin;
                if (tokA[i] >= 0) {
                    float* p = out + (size_t)tokA[i] * H_DIM + col;
                    atomicAdd(p,     wA[i] * acc[i][j][0]);
                    atomicAdd(p + 1, wA[i] * acc[i][j][1]);
                }
                if (tokB[i] >= 0) {
                    float* p = out + (size_t)tokB[i] * H_DIM + col;
                    atomicAdd(p,     wB[i] * acc[i][j][2]);
                    atomicAdd(p + 1, wB[i] * acc[i][j][3]);
                }
            }
    }
#undef LOAD_STAGE
}

// ---------------------------------------------------------------------------
extern "C" void kernel_launch(void* const* d_in, const int* in_sizes, int n_in,
                              void* d_out, int out_size) {
    const float* x  = (const float*)d_in[0];  // [4096, 1024]
    const float* gw = (const float*)d_in[1];  // [1024, 8]
    const float* Wg = (const float*)d_in[2];  // [8, 1024, 2048]
    const float* Wu = (const float*)d_in[3];  // [8, 1024, 2048]
    const float* Wd = (const float*)d_in[4];  // [8, 2048, 1024]
    float* out = (float*)d_out;               // final (4194304) then logits (32768)
    float* out_logits = out + (size_t)T_TOK * H_DIM;

    static cudaStream_t s_side = nullptr;
    static cudaEvent_t ev_fork = nullptr, ev_w1 = nullptr, ev_wd = nullptr;
    if (!s_side) {
        cudaStreamCreateWithFlags(&s_side, cudaStreamNonBlocking);
        cudaEventCreateWithFlags(&ev_fork, cudaEventDisableTiming);
        cudaEventCreateWithFlags(&ev_w1, cudaEventDisableTiming);
        cudaEventCreateWithFlags(&ev_wd, cudaEventDisableTiming);
        cudaFuncSetAttribute(mma_gemm_kernel<0>, cudaFuncAttributeMaxDynamicSharedMemorySize, SMEM_TOTAL);
        cudaFuncSetAttribute(mma_gemm_kernel<1>, cudaFuncAttributeMaxDynamicSharedMemorySize, SMEM_TOTAL);
    }

    // Fork: weight transposes on a side stream. GEMM1 needs only W1 (Wg+Wu);
    // Wd transposes during GEMM1 and gates only GEMM2 (split join events).
    cudaEventRecord(ev_fork, 0);
    cudaStreamWaitEvent(s_side, ev_fork, 0);
    wtrans_kernel<<<dim3(I_DIM / 32, H_DIM / 64, N_EXP), 256, 0, s_side>>>(Wg, 0);
    wtrans_kernel<<<dim3(I_DIM / 32, H_DIM / 64, N_EXP), 256, 0, s_side>>>(Wu, 1);
    cudaEventRecord(ev_w1, s_side);
    wtrans_kernel<<<dim3(H_DIM / 32, I_DIM / 64, N_EXP), 256, 0, s_side>>>(Wd, 2);
    cudaEventRecord(ev_wd, s_side);

    // Main stream: fused zero + convert + router (R12 layout), then scatter
    pre_kernel<<<8704, 256>>>(x, gw, out, out_logits);
    scatter_kernel<<<17, 256>>>();

    // GEMM1 (fused act): needs W1 only
    cudaStreamWaitEvent(0, ev_w1, 0);
    mma_gemm_kernel<0><<<dim3(NROWT, (2 * I_DIM) / BN), 256, SMEM_TOTAL>>>(nullptr);
    // GEMM2 (fused combine): needs Wd
    cudaStreamWaitEvent(0, ev_wd, 0);
    mma_gemm_kernel<1><<<dim3(NROWT, H_DIM / BN), 256, SMEM_TOTAL>>>(out);

    // Reset dispatch state for the next (graph-replayed) call
    tail_kernel<<<1, 32>>>();
}